// round 14
// baseline (speedup 1.0000x reference)
#include <cuda_runtime.h>
#include <cuda_fp16.h>
#include <math.h>
#include <stdint.h>

#define B_ 4
#define S_ 4096
#define D_ 512
#define F_ 2048
#define LN_EPS 1e-5f

#define BM 128
#define BN 128
#define BK 64
#define GT 256
#define KPAD_B 144                     // 64 fp16 = 128B padded to 144B (conflict-free ldmatrix)
#define TILE_B (128 * KPAD_B)          // 18432 B
#define OFF_A 0
#define OFF_B (TILE_B)
#define STAGE_B (2 * TILE_B)           // 36864
#define NSTAGE 3
#define SMEM_DYN (NSTAGE * STAGE_B)    // 110592 (x2 CTA = 221184 <= 228KB)

// ---------------- scratch ----------------
__device__ __align__(128) float g_scores[(size_t)B_ * S_ * S_];
__device__ __align__(128) float g_t2[(size_t)B_ * S_ * D_];
__device__ __align__(128) float g_x1[(size_t)B_ * S_ * D_];
__device__ __align__(128) float g_x2[(size_t)B_ * S_ * D_];
__device__ double g_part[(size_t)B_ * 256 * 2];
__device__ float g_stats[B_ * 2];

__device__ __align__(128) __half g_xh[(size_t)B_*S_*D_];
__device__ __align__(128) __half g_eh[(size_t)B_*S_*D_];
__device__ __align__(128) __half g_vth[(size_t)B_*D_*S_];
__device__ __align__(128) __half g_Ph[(size_t)B_*S_*S_];
__device__ __align__(128) __half g_t1h[(size_t)B_*S_*D_];
__device__ __align__(128) __half g_x2h[(size_t)B_*S_*D_];
__device__ __align__(128) __half g_hh[(size_t)B_*S_*F_];
__device__ __align__(128) __half g_wo1h[D_*D_], g_wo2h[D_*D_];
__device__ __align__(128) __half g_w1h[F_*D_],  g_w2h[D_*F_];

// ---------------- PTX helpers ----------------
__device__ __forceinline__ uint32_t smem_u32(const void* p) {
    return (uint32_t)__cvta_generic_to_shared(p);
}
__device__ __forceinline__ void cp16(uint32_t dst, const void* src) {
    asm volatile("cp.async.cg.shared.global [%0], [%1], 16;" :: "r"(dst), "l"(src));
}
__device__ __forceinline__ void cp_commit() {
    asm volatile("cp.async.commit_group;" ::: "memory");
}
__device__ __forceinline__ void ldsm4(uint32_t (&r)[4], uint32_t addr) {
    asm volatile("ldmatrix.sync.aligned.m8n8.x4.shared.b16 {%0,%1,%2,%3}, [%4];"
                 : "=r"(r[0]), "=r"(r[1]), "=r"(r[2]), "=r"(r[3]) : "r"(addr));
}
__device__ __forceinline__ void mma16816(float (&c)[4], const uint32_t (&a)[4],
                                         uint32_t b0, uint32_t b1) {
    asm volatile(
        "mma.sync.aligned.m16n8k16.row.col.f32.f16.f16.f32 "
        "{%0,%1,%2,%3}, {%4,%5,%6,%7}, {%8,%9}, {%0,%1,%2,%3};"
        : "+f"(c[0]), "+f"(c[1]), "+f"(c[2]), "+f"(c[3])
        : "r"(a[0]), "r"(a[1]), "r"(a[2]), "r"(a[3]), "r"(b0), "r"(b1));
}

// ---------------- stage loader: A, B -> padded smem (256 threads) ----------------
__device__ __forceinline__ void load_stage(uint32_t sb,
    const __half* Ap, const __half* Bp, int K, int kt, int tid)
{
#pragma unroll
    for (int j = 0; j < 4; j++) {
        const int idx = tid + j * 256;            // 0..1023
        const int row = idx >> 3, c = idx & 7;    // 128 rows x 8 chunks of 16B
        const size_t go = (size_t)row * K + kt + c * 8;
        const uint32_t so = row * KPAD_B + c * 16;
        cp16(sb + OFF_A + so, Ap + go);
        cp16(sb + OFF_B + so, Bp + go);
    }
}

// ---------------- tensor-core GEMM: D = alpha*A@B^T (+epilogue), fp16 ----------------
// EPI: 0 scale, 1 +res, 2 relu(+bias), 3 +bias+res
// MODE: 0 none, 1 causal, 2 clamp K to (by+1)*BM, 3 symmetric (coalesced mirror)
// OUTB: 0 -> fp32 C; 1 -> fp16 Ch
// STATS: 1 -> emit per-CTA (sum, sumsq) partials for joint LayerNorm
template<int EPI, int MODE, int OUTB, int STATS>
__global__ __launch_bounds__(GT, 2)
void gemm_mma(const __half* __restrict__ Ah, const __half* __restrict__ Bh,
              float* __restrict__ C, __half* __restrict__ Ch,
              const float* __restrict__ Rres, const float* __restrict__ bias,
              int M, int N, int K, float alpha,
              long long strideA, long long strideB, long long strideC)
{
    const int bx = blockIdx.x, bz = blockIdx.z;
    const int by = (MODE != 0) ? (gridDim.y - 1 - blockIdx.y) : blockIdx.y;
    if ((MODE == 1 || MODE == 3) && bx > by) return;

    extern __shared__ char smem[];
    const uint32_t sb0 = smem_u32(smem);

    const int tid = threadIdx.x;
    const int wid = tid >> 5, lane = tid & 31;
    const int warp_m = wid >> 2, warp_n = wid & 3;   // 2 x 4 warps; warp tile 64m x 32n
    const int lrow16 = lane & 15, lhi = lane >> 4;
    const int gr = lane >> 2, tg = lane & 3;

    const __half* Ap = Ah + (size_t)bz * strideA + (size_t)by * BM * K;
    const __half* Bp = Bh + (size_t)bz * strideB + (size_t)bx * BN * K;

    int kEnd = K;
    if (MODE == 2) { int ke = (by + 1) * BM; kEnd = ke < K ? ke : K; }
    const int nch = kEnd / BK;

    float acc[4][4][4];
#pragma unroll
    for (int mf = 0; mf < 4; mf++)
#pragma unroll
        for (int nf = 0; nf < 4; nf++)
#pragma unroll
            for (int r = 0; r < 4; r++) acc[mf][nf][r] = 0.f;

    const uint32_t a_lane = (uint32_t)((warp_m * 64 + lrow16) * KPAD_B + lhi * 16);
    const uint32_t b_lane = (uint32_t)((warp_n * 32 + lrow16) * KPAD_B + lhi * 16);

    // 3-stage prologue
    load_stage(sb0, Ap, Bp, K, 0, tid);
    cp_commit();
    if (nch > 1) {
        load_stage(sb0 + STAGE_B, Ap, Bp, K, BK, tid);
        cp_commit();
    }

    int sidx = 0;
    for (int c = 0; c < nch; ++c) {
        if (c + 1 < nch) {
            asm volatile("cp.async.wait_group 1;" ::: "memory");   // stage c landed
        } else {
            asm volatile("cp.async.wait_group 0;" ::: "memory");
        }
        __syncthreads();   // all warps done with stage (c+2)%3's previous contents
        if (c + 2 < nch) {
            int ls = sidx + 2; if (ls >= NSTAGE) ls -= NSTAGE;
            load_stage(sb0 + ls * STAGE_B, Ap, Bp, K, (c + 2) * BK, tid);
            cp_commit();
        }

        const uint32_t buf = sb0 + sidx * STAGE_B;
#pragma unroll
        for (int ks = 0; ks < 4; ks++) {
            uint32_t a_h[4][4], b_h[2][4];
#pragma unroll
            for (int mf = 0; mf < 4; mf++) {
                const uint32_t ad = buf + a_lane + (uint32_t)(mf * 16 * KPAD_B + ks * 32);
                ldsm4(a_h[mf], ad + OFF_A);
            }
#pragma unroll
            for (int hN = 0; hN < 2; hN++) {
                const uint32_t bd = buf + b_lane + (uint32_t)(hN * 16 * KPAD_B + ks * 32);
                ldsm4(b_h[hN], bd + OFF_B);
            }
#pragma unroll
            for (int mf = 0; mf < 4; mf++) {
#pragma unroll
                for (int nf = 0; nf < 4; nf++) {
                    const uint32_t bh0 = b_h[nf >> 1][nf & 1], bh1 = b_h[nf >> 1][2 + (nf & 1)];
                    mma16816(acc[mf][nf], a_h[mf], bh0, bh1);
                }
            }
        }
        sidx++; if (sidx == NSTAGE) sidx = 0;
    }

    // MODE 3 reuses pipeline smem as a transpose tile: wait for ALL warps to
    // finish reading stage smem before overwriting it.
    if (MODE == 3) __syncthreads();

    // ---------------- epilogue ----------------
    float ls = 0.f, ls2 = 0.f;
#pragma unroll
    for (int mf = 0; mf < 4; mf++) {
#pragma unroll
        for (int nf = 0; nf < 4; nf++) {
#pragma unroll
            for (int half = 0; half < 2; half++) {
                const int row = by * BM + warp_m * 64 + mf * 16 + gr + half * 8;
                const int col = bx * BN + warp_n * 32 + nf * 8 + tg * 2;
                float v0 = acc[mf][nf][half * 2 + 0] * alpha;
                float v1 = acc[mf][nf][half * 2 + 1] * alpha;
                if (EPI == 2 || EPI == 3) {
                    const float2 bb = *reinterpret_cast<const float2*>(&bias[col]);
                    v0 += bb.x; v1 += bb.y;
                }
                const size_t o = (size_t)bz * strideC + (size_t)row * N + col;
                if (EPI == 1 || EPI == 3) {
                    const float2 rr = *reinterpret_cast<const float2*>(&Rres[o]);
                    v0 += rr.x; v1 += rr.y;
                }
                if (EPI == 2) { v0 = fmaxf(v0, 0.f); v1 = fmaxf(v1, 0.f); }
                if (STATS) { ls += v0 + v1; ls2 += v0 * v0 + v1 * v1; }
                if (OUTB == 0) {
                    float2 st; st.x = v0; st.y = v1;
                    *reinterpret_cast<float2*>(&C[o]) = st;
                } else {
                    __half2 hv = __floats2half2_rn(v0, v1);
                    *reinterpret_cast<uint32_t*>(&Ch[o]) =
                        *reinterpret_cast<const uint32_t*>(&hv);
                }
                // store to smem transpose tile for coalesced mirror (MODE 3)
                if (MODE == 3) {
                    float* t = reinterpret_cast<float*>(smem);   // [128][132]
                    const int lr = warp_m * 64 + mf * 16 + gr + half * 8;
                    const int lc = warp_n * 32 + nf * 8 + tg * 2;
                    t[(size_t)lc * 132 + lr]       = v0;
                    t[(size_t)(lc + 1) * 132 + lr] = v1;
                }
            }
        }
    }

    if (MODE == 3) {
        // coalesced transposed write: C[bx*128 + r][by*128 + ...]
        __syncthreads();
        const float* t = reinterpret_cast<const float*>(smem);
        float* Cm = C + (size_t)bz * strideC;
#pragma unroll
        for (int it = 0; it < 16; it++) {
            const int idx = tid + it * 256;          // 0..4095
            const int r = idx >> 5, c4 = idx & 31;   // 128 rows x 32 float4
            float4 v = *reinterpret_cast<const float4*>(&t[(size_t)r * 132 + c4 * 4]);
            *reinterpret_cast<float4*>(
                &Cm[(size_t)(bx * BN + r) * N + by * BM + c4 * 4]) = v;
        }
    }

    if (STATS) {
        __syncthreads();
        double* sh  = reinterpret_cast<double*>(smem);
        double* sh2 = sh + GT;
        sh[tid] = (double)ls; sh2[tid] = (double)ls2;
        __syncthreads();
        for (int o = GT / 2; o > 0; o >>= 1) {
            if (tid < o) { sh[tid] += sh[tid + o]; sh2[tid] += sh2[tid + o]; }
            __syncthreads();
        }
        if (tid == 0) {
            const int batch = by >> 5;
            const int slot = ((by & 31) << 2) | bx;
            g_part[((size_t)batch * 256 + slot) * 2]     = sh[0];
            g_part[((size_t)batch * 256 + slot) * 2 + 1] = sh2[0];
        }
    }
}

// ---------------- softmax: fp32 scores -> fp16 P ----------------
template<int CAUSAL>
__global__ void softmax_half_kernel(const float* __restrict__ Sc,
                                    __half* __restrict__ Ph)
{
    const int T = 256, NC = S_ / T;
    const int row = blockIdx.x, b = blockIdx.y, t = threadIdx.x;
    const float* rp = Sc + ((size_t)b * S_ + row) * S_;
    __half* hp = Ph + ((size_t)b * S_ + row) * S_;
    const int limit = CAUSAL ? row + 1 : S_;
    const int blockEnd = CAUSAL ? (((row >> 7) + 1) << 7) : S_;

    float v[NC];
#pragma unroll
    for (int c = 0; c < NC; c++) {
        int j = t + c * T;
        v[c] = (j < limit) ? rp[j] : -INFINITY;
    }
    float m = -INFINITY;
#pragma unroll
    for (int c = 0; c < NC; c++) m = fmaxf(m, v[c]);
#pragma unroll
    for (int o = 16; o > 0; o >>= 1) m = fmaxf(m, __shfl_xor_sync(0xffffffffu, m, o));
    __shared__ float sred[8];
    if ((t & 31) == 0) sred[t >> 5] = m;
    __syncthreads();
    m = sred[0];
#pragma unroll
    for (int w = 1; w < 8; w++) m = fmaxf(m, sred[w]);
    __syncthreads();

    float s = 0.f;
#pragma unroll
    for (int c = 0; c < NC; c++) { float e = __expf(v[c] - m); v[c] = e; s += e; }
#pragma unroll
    for (int o = 16; o > 0; o >>= 1) s += __shfl_xor_sync(0xffffffffu, s, o);
    if ((t & 31) == 0) sred[t >> 5] = s;
    __syncthreads();
    s = 0.f;
#pragma unroll
    for (int w = 0; w < 8; w++) s += sred[w];
    const float inv = 1.f / s;
#pragma unroll
    for (int c = 0; c < NC; c++) {
        int j = t + c * T;
        if (j < blockEnd) hp[j] = __float2half_rn(v[c] * inv);
    }
}

// ---------------- elementwise fp32 -> fp16 ----------------
__global__ void half_kernel(const float* __restrict__ X, __half* __restrict__ H)
{
    const size_t i = ((size_t)blockIdx.x * 256 + threadIdx.x) * 4;
    float4 v = *reinterpret_cast<const float4*>(X + i);
    __half2 a = __floats2half2_rn(v.x, v.y);
    __half2 b = __floats2half2_rn(v.z, v.w);
    uint2 hv;
    hv.x = *reinterpret_cast<const uint32_t*>(&a);
    hv.y = *reinterpret_cast<const uint32_t*>(&b);
    *reinterpret_cast<uint2*>(H + i) = hv;
}

// ---------------- merged weight converts ----------------
__global__ void weights_half_kernel(const float* __restrict__ Wo1, const float* __restrict__ Wo2,
                                    const float* __restrict__ W1,  const float* __restrict__ W2,
                                    __half* __restrict__ wo1h, __half* __restrict__ wo2h,
                                    __half* __restrict__ w1h,  __half* __restrict__ w2h)
{
    const size_t i = ((size_t)blockIdx.x * 256 + threadIdx.x) * 4;
    const size_t n1 = D_ * D_, n2 = 2 * n1, n3 = n2 + F_ * D_;
    const float* src; __half* dst; size_t off;
    if (i < n1)      { src = Wo1; dst = wo1h; off = i; }
    else if (i < n2) { src = Wo2; dst = wo2h; off = i - n1; }
    else if (i < n3) { src = W1;  dst = w1h;  off = i - n2; }
    else             { src = W2;  dst = w2h;  off = i - n3; }
    float4 v = *reinterpret_cast<const float4*>(src + off);
    __half2 a = __floats2half2_rn(v.x, v.y);
    __half2 b = __floats2half2_rn(v.z, v.w);
    uint2 hv;
    hv.x = *reinterpret_cast<const uint32_t*>(&a);
    hv.y = *reinterpret_cast<const uint32_t*>(&b);
    *reinterpret_cast<uint2*>(dst + off) = hv;
}

// ---------------- fused: fp32 [B,S,D] -> fp16 row-major + fp16 transposed ----------------
__global__ void conv_half_tr_kernel(const float* __restrict__ X,
                                    __half* __restrict__ H, __half* __restrict__ Th)
{
    __shared__ float t[32][33];
    const int b = blockIdx.z;
    const int d0 = blockIdx.x * 32, s0 = blockIdx.y * 32;
    const float* Xp = X + (size_t)b * S_ * D_;
    __half* Hp = H + (size_t)b * S_ * D_;
    for (int i = threadIdx.y; i < 32; i += 8) {
        const size_t sd = (size_t)(s0 + i) * D_ + d0 + threadIdx.x;
        float v = Xp[sd];
        t[i][threadIdx.x] = v;
        Hp[sd] = __float2half_rn(v);
    }
    __syncthreads();
    for (int i = threadIdx.y; i < 32; i += 8) {
        size_t o = (size_t)b * D_ * S_ + (size_t)(d0 + i) * S_ + s0 + threadIdx.x;
        Th[o] = __float2half_rn(t[threadIdx.x][i]);
    }
}

// ---------------- fused: LN-apply + fp32 out + fp16 transposed out ----------------
__global__ void ln_apply_tr_kernel(const float* __restrict__ X, const float* __restrict__ G,
                                   const float* __restrict__ Be,
                                   float* __restrict__ Y, __half* __restrict__ Th)
{
    __shared__ float t[32][33];
    const int b = blockIdx.z;
    const int d0 = blockIdx.x * 32, s0 = blockIdx.y * 32;
    const float mu = g_stats[b * 2], rs = g_stats[b * 2 + 1];
    const float* Xp = X + (size_t)b * S_ * D_;
    float* Yp = Y + (size_t)b * S_ * D_;
    for (int i = threadIdx.y; i < 32; i += 8) {
        const size_t sd = (size_t)(s0 + i) * D_ + d0 + threadIdx.x;
        float y = (Xp[sd] - mu) * rs * G[sd] + Be[sd];
        t[i][threadIdx.x] = y;
        Yp[sd] = y;
    }
    __syncthreads();
    for (int i = threadIdx.y; i < 32; i += 8) {
        size_t o = (size_t)b * D_ * S_ + (size_t)(d0 + i) * S_ + s0 + threadIdx.x;
        Th[o] = __float2half_rn(t[threadIdx.x][i]);
    }
}

// ---------------- LN final reduce ----------------
__global__ void ln_reduce2_kernel()
{
    const int b = blockIdx.x;
    const int t = threadIdx.x;
    double s  = (t < 128) ? g_part[((size_t)b * 256 + t) * 2]     : 0.0;
    double s2 = (t < 128) ? g_part[((size_t)b * 256 + t) * 2 + 1] : 0.0;
    __shared__ double sh[256], sh2[256];
    sh[t] = s; sh2[t] = s2;
    __syncthreads();
    for (int o = 128; o > 0; o >>= 1) {
        if (t < o) { sh[t] += sh[t + o]; sh2[t] += sh2[t + o]; }
        __syncthreads();
    }
    if (t == 0) {
        const double n = (double)S_ * (double)D_;
        double mu  = sh[0] / n;
        double var = sh2[0] / n - mu * mu;
        g_stats[b * 2]     = (float)mu;
        g_stats[b * 2 + 1] = (float)(1.0 / sqrt(var + (double)LN_EPS));
    }
}

__global__ void ln_apply_kernel(const float* __restrict__ X, const float* __restrict__ G,
                                const float* __restrict__ Be, float* __restrict__ Y)
{
    const size_t idx = (size_t)blockIdx.x * blockDim.x + threadIdx.x;
    const size_t sd = idx & ((size_t)S_ * D_ - 1);
    const int b = (int)(idx >> 21);
    const float mu = g_stats[b * 2], rs = g_stats[b * 2 + 1];
    Y[idx] = (X[idx] - mu) * rs * G[sd] + Be[sd];
}

__global__ void ln_apply_half_kernel(const float* __restrict__ X, const float* __restrict__ G,
                                     const float* __restrict__ Be, float* __restrict__ Y,
                                     __half* __restrict__ Yh)
{
    const size_t idx = (size_t)blockIdx.x * blockDim.x + threadIdx.x;
    const size_t sd = idx & ((size_t)S_ * D_ - 1);
    const int b = (int)(idx >> 21);
    const float mu = g_stats[b * 2], rs = g_stats[b * 2 + 1];
    float y = (X[idx] - mu) * rs * G[sd] + Be[sd];
    Y[idx] = y;
    Yh[idx] = __float2half_rn(y);
}

// ---------------- orchestration ----------------
extern "C" void kernel_launch(void* const* d_in, const int* in_sizes, int n_in,
                              void* d_out, int out_size)
{
    (void)in_sizes; (void)n_in; (void)out_size;
    const float* x    = (const float*)d_in[0];
    const float* enc  = (const float*)d_in[1];
    const float* Wo1  = (const float*)d_in[2];
    const float* Wo2  = (const float*)d_in[3];
    const float* ln1g = (const float*)d_in[4];
    const float* ln1b = (const float*)d_in[5];
    const float* ln2g = (const float*)d_in[6];
    const float* ln2b = (const float*)d_in[7];
    const float* W1   = (const float*)d_in[8];
    const float* b1   = (const float*)d_in[9];
    const float* W2   = (const float*)d_in[10];
    const float* b2   = (const float*)d_in[11];
    float* out = (float*)d_out;

    float *scores, *t2, *x1, *x2;
    cudaGetSymbolAddress((void**)&scores, g_scores);
    cudaGetSymbolAddress((void**)&t2, g_t2);
    cudaGetSymbolAddress((void**)&x1, g_x1);
    cudaGetSymbolAddress((void**)&x2, g_x2);
    __half *xh, *eh, *vth, *Ph, *t1h, *x2h, *hh;
    __half *wo1h, *wo2h, *w1h, *w2h;
    cudaGetSymbolAddress((void**)&xh, g_xh);
    cudaGetSymbolAddress((void**)&eh, g_eh);
    cudaGetSymbolAddress((void**)&vth, g_vth);
    cudaGetSymbolAddress((void**)&Ph, g_Ph);
    cudaGetSymbolAddress((void**)&t1h, g_t1h);
    cudaGetSymbolAddress((void**)&x2h, g_x2h);
    cudaGetSymbolAddress((void**)&hh, g_hh);
    cudaGetSymbolAddress((void**)&wo1h, g_wo1h); cudaGetSymbolAddress((void**)&wo2h, g_wo2h);
    cudaGetSymbolAddress((void**)&w1h, g_w1h);   cudaGetSymbolAddress((void**)&w2h, g_w2h);

    cudaFuncSetAttribute(gemm_mma<0,1,0,0>, cudaFuncAttributeMaxDynamicSharedMemorySize, SMEM_DYN);
    cudaFuncSetAttribute(gemm_mma<0,3,0,0>, cudaFuncAttributeMaxDynamicSharedMemorySize, SMEM_DYN);
    cudaFuncSetAttribute(gemm_mma<0,2,1,0>, cudaFuncAttributeMaxDynamicSharedMemorySize, SMEM_DYN);
    cudaFuncSetAttribute(gemm_mma<0,0,1,0>, cudaFuncAttributeMaxDynamicSharedMemorySize, SMEM_DYN);
    cudaFuncSetAttribute(gemm_mma<1,0,0,1>, cudaFuncAttributeMaxDynamicSharedMemorySize, SMEM_DYN);
    cudaFuncSetAttribute(gemm_mma<2,0,1,0>, cudaFuncAttributeMaxDynamicSharedMemorySize, SMEM_DYN);
    cudaFuncSetAttribute(gemm_mma<3,0,0,1>, cudaFuncAttributeMaxDynamicSharedMemorySize, SMEM_DYN);

    const dim3 blk(256);
    const dim3 gblk(GT);
    const float scale = 1.0f / sqrtf((float)D_);
    const long long sSS = (long long)S_ * S_;
    const long long sSD = (long long)S_ * D_;
    const long long sDS = (long long)D_ * S_;
    const int lnBlocks = (B_ * S_ * D_) / 256;
    const size_t nBSD = (size_t)B_ * S_ * D_;

    // ---- operand conversions ----
    conv_half_tr_kernel<<<dim3(D_ / 32, S_ / 32, B_), dim3(32, 8)>>>(x, xh, vth);
    half_kernel<<<(int)(nBSD / 1024), blk>>>(enc, eh);
    weights_half_kernel<<<(2 * D_ * D_ + 2 * F_ * D_) / 1024, blk>>>(
        Wo1, Wo2, W1, W2, wo1h, wo2h, w1h, w2h);

    // ---- 1) causal self-attention + Wo1 + residual + ln1 ----
    gemm_mma<0,1,0,0><<<dim3(S_ / BN, S_ / BM, B_), gblk, SMEM_DYN>>>(
        xh, xh, scores, nullptr, nullptr, nullptr,
        S_, S_, D_, scale, sSD, sSD, sSS);
    softmax_half_kernel<1><<<dim3(S_, B_), blk>>>(scores, Ph);
    gemm_mma<0,2,1,0><<<dim3(D_ / BN, S_ / BM, B_), gblk, SMEM_DYN>>>(
        Ph, vth, nullptr, t1h, nullptr, nullptr,
        S_, D_, S_, 1.f, sSS, sDS, sSD);
    gemm_mma<1,0,0,1><<<dim3(D_ / BN, (B_ * S_) / BM, 1), gblk, SMEM_DYN>>>(
        t1h, wo1h, t2, nullptr, x, nullptr,
        B_ * S_, D_, D_, 1.f, 0, 0, 0);
    ln_reduce2_kernel<<<B_, blk>>>();
    ln_apply_tr_kernel<<<dim3(D_ / 32, S_ / 32, B_), dim3(32, 8)>>>(t2, ln1g, ln1b, x1, vth);

    // ---- 2) cross attention (q=k=enc, v=x1): scores symmetric -> half the blocks ----
    gemm_mma<0,3,0,0><<<dim3(S_ / BN, S_ / BM, B_), gblk, SMEM_DYN>>>(
        eh, eh, scores, nullptr, nullptr, nullptr,
        S_, S_, D_, scale, sSD, sSD, sSS);
    softmax_half_kernel<0><<<dim3(S_, B_), blk>>>(scores, Ph);
    gemm_mma<0,0,1,0><<<dim3(D_ / BN, S_ / BM, B_), gblk, SMEM_DYN>>>(
        Ph, vth, nullptr, t1h, nullptr, nullptr,
        S_, D_, S_, 1.f, sSS, sDS, sSD);
    gemm_mma<1,0,0,1><<<dim3(D_ / BN, (B_ * S_) / BM, 1), gblk, SMEM_DYN>>>(
        t1h, wo2h, t2, nullptr, x1, nullptr,
        B_ * S_, D_, D_, 1.f, 0, 0, 0);
    ln_reduce2_kernel<<<B_, blk>>>();
    ln_apply_half_kernel<<<lnBlocks, blk>>>(t2, ln2g, ln2b, x2, x2h);

    // ---- 3) FFN + residual + ln2 (shared params) ----
    gemm_mma<2,0,1,0><<<dim3(F_ / BN, (B_ * S_) / BM, 1), gblk, SMEM_DYN>>>(
        x2h, w1h, nullptr, hh, nullptr, b1,
        B_ * S_, F_, D_, 1.f, 0, 0, 0);
    gemm_mma<3,0,0,1><<<dim3(D_ / BN, (B_ * S_) / BM, 1), gblk, SMEM_DYN>>>(
        hh, w2h, t2, nullptr, x2, b2,
        B_ * S_, D_, F_, 1.f, 0, 0, 0);
    ln_reduce2_kernel<<<B_, blk>>>();
    ln_apply_kernel<<<lnBlocks, blk>>>(t2, ln2g, ln2b, out);
}

// round 15
// speedup vs baseline: 1.0166x; 1.0166x over previous
#include <cuda_runtime.h>
#include <cuda_fp16.h>
#include <math.h>
#include <stdint.h>

#define B_ 4
#define S_ 4096
#define D_ 512
#define F_ 2048
#define LN_EPS 1e-5f

#define BM 128
#define BN 128
#define BK 64
#define GT 256
#define KPAD_B 144                     // 64 fp16 = 128B padded to 144B (conflict-free ldmatrix)
#define TILE_B (128 * KPAD_B)          // 18432 B
#define OFF_A 0
#define OFF_B (TILE_B)
#define STAGE_B (2 * TILE_B)           // 36864
#define SMEM_DYN (2 * STAGE_B)         // 73728 (transpose tile 128*132*4=67584 fits)

// ---------------- scratch ----------------
__device__ __align__(128) float g_scores[(size_t)B_ * S_ * S_];
__device__ __align__(128) float g_t2[(size_t)B_ * S_ * D_];
__device__ __align__(128) float g_x1[(size_t)B_ * S_ * D_];
__device__ __align__(128) float g_x2[(size_t)B_ * S_ * D_];
__device__ double g_part[(size_t)B_ * 256 * 2];
__device__ float g_stats[B_ * 2];

__device__ __align__(128) __half g_xh[(size_t)B_*S_*D_];
__device__ __align__(128) __half g_eh[(size_t)B_*S_*D_];
__device__ __align__(128) __half g_vth[(size_t)B_*D_*S_];
__device__ __align__(128) __half g_Ph[(size_t)B_*S_*S_];
__device__ __align__(128) __half g_t1h[(size_t)B_*S_*D_];
__device__ __align__(128) __half g_x2h[(size_t)B_*S_*D_];
__device__ __align__(128) __half g_hh[(size_t)B_*S_*F_];
__device__ __align__(128) __half g_wo1h[D_*D_], g_wo2h[D_*D_];
__device__ __align__(128) __half g_w1h[F_*D_],  g_w2h[D_*F_];

// ---------------- PTX helpers ----------------
__device__ __forceinline__ uint32_t smem_u32(const void* p) {
    return (uint32_t)__cvta_generic_to_shared(p);
}
__device__ __forceinline__ void cp16(uint32_t dst, const void* src) {
    asm volatile("cp.async.cg.shared.global [%0], [%1], 16;" :: "r"(dst), "l"(src));
}
__device__ __forceinline__ void cp_commit() {
    asm volatile("cp.async.commit_group;" ::: "memory");
}
__device__ __forceinline__ void ldsm4(uint32_t (&r)[4], uint32_t addr) {
    asm volatile("ldmatrix.sync.aligned.m8n8.x4.shared.b16 {%0,%1,%2,%3}, [%4];"
                 : "=r"(r[0]), "=r"(r[1]), "=r"(r[2]), "=r"(r[3]) : "r"(addr));
}
__device__ __forceinline__ void mma16816(float (&c)[4], const uint32_t (&a)[4],
                                         uint32_t b0, uint32_t b1) {
    asm volatile(
        "mma.sync.aligned.m16n8k16.row.col.f32.f16.f16.f32 "
        "{%0,%1,%2,%3}, {%4,%5,%6,%7}, {%8,%9}, {%0,%1,%2,%3};"
        : "+f"(c[0]), "+f"(c[1]), "+f"(c[2]), "+f"(c[3])
        : "r"(a[0]), "r"(a[1]), "r"(a[2]), "r"(a[3]), "r"(b0), "r"(b1));
}

// ---------------- stage loader: A, B -> padded smem (256 threads) ----------------
__device__ __forceinline__ void load_stage(uint32_t sb,
    const __half* Ap, const __half* Bp, int K, int kt, int tid)
{
#pragma unroll
    for (int j = 0; j < 4; j++) {
        const int idx = tid + j * 256;            // 0..1023
        const int row = idx >> 3, c = idx & 7;    // 128 rows x 8 chunks of 16B
        const size_t go = (size_t)row * K + kt + c * 8;
        const uint32_t so = row * KPAD_B + c * 16;
        cp16(sb + OFF_A + so, Ap + go);
        cp16(sb + OFF_B + so, Bp + go);
    }
}

// ---------------- tensor-core GEMM: D = alpha*A@B^T (+epilogue), fp16 ----------------
// EPI: 0 scale, 1 +res, 2 relu(+bias), 3 +bias+res
// MODE: 0 none, 1 causal, 2 clamp K to (by+1)*BM, 3 symmetric (coalesced mirror)
// OUTB: 0 -> fp32 C; 1 -> fp16 Ch
// STATS: 1 -> emit per-CTA (sum, sumsq) partials for joint LayerNorm
template<int EPI, int MODE, int OUTB, int STATS>
__global__ __launch_bounds__(GT, 2)
void gemm_mma(const __half* __restrict__ Ah, const __half* __restrict__ Bh,
              float* __restrict__ C, __half* __restrict__ Ch,
              const float* __restrict__ Rres, const float* __restrict__ bias,
              int M, int N, int K, float alpha,
              long long strideA, long long strideB, long long strideC)
{
    const int bx = blockIdx.x, bz = blockIdx.z;
    const int by = (MODE != 0) ? (gridDim.y - 1 - blockIdx.y) : blockIdx.y;
    if ((MODE == 1 || MODE == 3) && bx > by) return;

    extern __shared__ char smem[];
    const uint32_t sb0 = smem_u32(smem);

    const int tid = threadIdx.x;
    const int wid = tid >> 5, lane = tid & 31;
    const int warp_m = wid >> 2, warp_n = wid & 3;   // 2 x 4 warps; warp tile 64m x 32n
    const int lrow16 = lane & 15, lhi = lane >> 4;
    const int gr = lane >> 2, tg = lane & 3;

    const __half* Ap = Ah + (size_t)bz * strideA + (size_t)by * BM * K;
    const __half* Bp = Bh + (size_t)bz * strideB + (size_t)bx * BN * K;

    int kEnd = K;
    if (MODE == 2) { int ke = (by + 1) * BM; kEnd = ke < K ? ke : K; }
    const int nch = kEnd / BK;

    float acc[4][4][4];
#pragma unroll
    for (int mf = 0; mf < 4; mf++)
#pragma unroll
        for (int nf = 0; nf < 4; nf++)
#pragma unroll
            for (int r = 0; r < 4; r++) acc[mf][nf][r] = 0.f;

    const uint32_t a_lane = (uint32_t)((warp_m * 64 + lrow16) * KPAD_B + lhi * 16);
    const uint32_t b_lane = (uint32_t)((warp_n * 32 + lrow16) * KPAD_B + lhi * 16);

    load_stage(sb0, Ap, Bp, K, 0, tid);
    cp_commit();

    for (int c = 0; c < nch; ++c) {
        asm volatile("cp.async.wait_group 0;" ::: "memory");
        __syncthreads();
        if (c + 1 < nch) {
            load_stage(sb0 + ((c + 1) & 1) * STAGE_B, Ap, Bp, K, (c + 1) * BK, tid);
            cp_commit();
        }

        const uint32_t buf = sb0 + (c & 1) * STAGE_B;
#pragma unroll
        for (int ks = 0; ks < 4; ks++) {
            uint32_t a_h[4][4], b_h[2][4];
#pragma unroll
            for (int mf = 0; mf < 4; mf++) {
                const uint32_t ad = buf + a_lane + (uint32_t)(mf * 16 * KPAD_B + ks * 32);
                ldsm4(a_h[mf], ad + OFF_A);
            }
#pragma unroll
            for (int hN = 0; hN < 2; hN++) {
                const uint32_t bd = buf + b_lane + (uint32_t)(hN * 16 * KPAD_B + ks * 32);
                ldsm4(b_h[hN], bd + OFF_B);
            }
#pragma unroll
            for (int mf = 0; mf < 4; mf++) {
#pragma unroll
                for (int nf = 0; nf < 4; nf++) {
                    const uint32_t bh0 = b_h[nf >> 1][nf & 1], bh1 = b_h[nf >> 1][2 + (nf & 1)];
                    mma16816(acc[mf][nf], a_h[mf], bh0, bh1);
                }
            }
        }
        __syncthreads();
    }

    // ---------------- epilogue ----------------
    float ls = 0.f, ls2 = 0.f;
#pragma unroll
    for (int mf = 0; mf < 4; mf++) {
#pragma unroll
        for (int nf = 0; nf < 4; nf++) {
#pragma unroll
            for (int half = 0; half < 2; half++) {
                const int row = by * BM + warp_m * 64 + mf * 16 + gr + half * 8;
                const int col = bx * BN + warp_n * 32 + nf * 8 + tg * 2;
                float v0 = acc[mf][nf][half * 2 + 0] * alpha;
                float v1 = acc[mf][nf][half * 2 + 1] * alpha;
                if (EPI == 2 || EPI == 3) {
                    const float2 bb = *reinterpret_cast<const float2*>(&bias[col]);
                    v0 += bb.x; v1 += bb.y;
                }
                const size_t o = (size_t)bz * strideC + (size_t)row * N + col;
                if (EPI == 1 || EPI == 3) {
                    const float2 rr = *reinterpret_cast<const float2*>(&Rres[o]);
                    v0 += rr.x; v1 += rr.y;
                }
                if (EPI == 2) { v0 = fmaxf(v0, 0.f); v1 = fmaxf(v1, 0.f); }
                if (STATS) { ls += v0 + v1; ls2 += v0 * v0 + v1 * v1; }
                if (OUTB == 0) {
                    float2 st; st.x = v0; st.y = v1;
                    *reinterpret_cast<float2*>(&C[o]) = st;
                } else {
                    __half2 hv = __floats2half2_rn(v0, v1);
                    *reinterpret_cast<uint32_t*>(&Ch[o]) =
                        *reinterpret_cast<const uint32_t*>(&hv);
                }
                // store to smem transpose tile for coalesced mirror (MODE 3)
                if (MODE == 3) {
                    float* t = reinterpret_cast<float*>(smem);   // [128][132]
                    const int lr = warp_m * 64 + mf * 16 + gr + half * 8;
                    const int lc = warp_n * 32 + nf * 8 + tg * 2;
                    t[(size_t)lc * 132 + lr]       = v0;
                    t[(size_t)(lc + 1) * 132 + lr] = v1;
                }
            }
        }
    }
    // NOTE: main loop's trailing __syncthreads() guarantees no warp is still
    // reading stage smem when the MODE-3 transpose-tile writes above happen.

    if (MODE == 3) {
        // coalesced transposed write: C[bx*128 + r][by*128 + ...]
        __syncthreads();
        const float* t = reinterpret_cast<const float*>(smem);
        float* Cm = C + (size_t)bz * strideC;
#pragma unroll
        for (int it = 0; it < 16; it++) {
            const int idx = tid + it * 256;          // 0..4095
            const int r = idx >> 5, c4 = idx & 31;   // 128 rows x 32 float4
            float4 v = *reinterpret_cast<const float4*>(&t[(size_t)r * 132 + c4 * 4]);
            *reinterpret_cast<float4*>(
                &Cm[(size_t)(bx * BN + r) * N + by * BM + c4 * 4]) = v;
        }
    }

    if (STATS) {
        __syncthreads();
        double* sh  = reinterpret_cast<double*>(smem);
        double* sh2 = sh + GT;
        sh[tid] = (double)ls; sh2[tid] = (double)ls2;
        __syncthreads();
        for (int o = GT / 2; o > 0; o >>= 1) {
            if (tid < o) { sh[tid] += sh[tid + o]; sh2[tid] += sh2[tid + o]; }
            __syncthreads();
        }
        if (tid == 0) {
            const int batch = by >> 5;
            const int slot = ((by & 31) << 2) | bx;
            g_part[((size_t)batch * 256 + slot) * 2]     = sh[0];
            g_part[((size_t)batch * 256 + slot) * 2 + 1] = sh2[0];
        }
    }
}

// ---------------- softmax: fp32 scores -> fp16 P ----------------
template<int CAUSAL>
__global__ void softmax_half_kernel(const float* __restrict__ Sc,
                                    __half* __restrict__ Ph)
{
    const int T = 256, NC = S_ / T;
    const int row = blockIdx.x, b = blockIdx.y, t = threadIdx.x;
    const float* rp = Sc + ((size_t)b * S_ + row) * S_;
    __half* hp = Ph + ((size_t)b * S_ + row) * S_;
    const int limit = CAUSAL ? row + 1 : S_;
    const int blockEnd = CAUSAL ? (((row >> 7) + 1) << 7) : S_;

    float v[NC];
#pragma unroll
    for (int c = 0; c < NC; c++) {
        int j = t + c * T;
        v[c] = (j < limit) ? rp[j] : -INFINITY;
    }
    float m = -INFINITY;
#pragma unroll
    for (int c = 0; c < NC; c++) m = fmaxf(m, v[c]);
#pragma unroll
    for (int o = 16; o > 0; o >>= 1) m = fmaxf(m, __shfl_xor_sync(0xffffffffu, m, o));
    __shared__ float sred[8];
    if ((t & 31) == 0) sred[t >> 5] = m;
    __syncthreads();
    m = sred[0];
#pragma unroll
    for (int w = 1; w < 8; w++) m = fmaxf(m, sred[w]);
    __syncthreads();

    float s = 0.f;
#pragma unroll
    for (int c = 0; c < NC; c++) { float e = __expf(v[c] - m); v[c] = e; s += e; }
#pragma unroll
    for (int o = 16; o > 0; o >>= 1) s += __shfl_xor_sync(0xffffffffu, s, o);
    if ((t & 31) == 0) sred[t >> 5] = s;
    __syncthreads();
    s = 0.f;
#pragma unroll
    for (int w = 0; w < 8; w++) s += sred[w];
    const float inv = 1.f / s;
#pragma unroll
    for (int c = 0; c < NC; c++) {
        int j = t + c * T;
        if (j < blockEnd) hp[j] = __float2half_rn(v[c] * inv);
    }
}

// ---------------- elementwise fp32 -> fp16 ----------------
__global__ void half_kernel(const float* __restrict__ X, __half* __restrict__ H)
{
    const size_t i = ((size_t)blockIdx.x * 256 + threadIdx.x) * 4;
    float4 v = *reinterpret_cast<const float4*>(X + i);
    __half2 a = __floats2half2_rn(v.x, v.y);
    __half2 b = __floats2half2_rn(v.z, v.w);
    uint2 hv;
    hv.x = *reinterpret_cast<const uint32_t*>(&a);
    hv.y = *reinterpret_cast<const uint32_t*>(&b);
    *reinterpret_cast<uint2*>(H + i) = hv;
}

// ---------------- merged weight converts ----------------
__global__ void weights_half_kernel(const float* __restrict__ Wo1, const float* __restrict__ Wo2,
                                    const float* __restrict__ W1,  const float* __restrict__ W2,
                                    __half* __restrict__ wo1h, __half* __restrict__ wo2h,
                                    __half* __restrict__ w1h,  __half* __restrict__ w2h)
{
    const size_t i = ((size_t)blockIdx.x * 256 + threadIdx.x) * 4;
    const size_t n1 = D_ * D_, n2 = 2 * n1, n3 = n2 + F_ * D_;
    const float* src; __half* dst; size_t off;
    if (i < n1)      { src = Wo1; dst = wo1h; off = i; }
    else if (i < n2) { src = Wo2; dst = wo2h; off = i - n1; }
    else if (i < n3) { src = W1;  dst = w1h;  off = i - n2; }
    else             { src = W2;  dst = w2h;  off = i - n3; }
    float4 v = *reinterpret_cast<const float4*>(src + off);
    __half2 a = __floats2half2_rn(v.x, v.y);
    __half2 b = __floats2half2_rn(v.z, v.w);
    uint2 hv;
    hv.x = *reinterpret_cast<const uint32_t*>(&a);
    hv.y = *reinterpret_cast<const uint32_t*>(&b);
    *reinterpret_cast<uint2*>(dst + off) = hv;
}

// ---------------- fused: fp32 [B,S,D] -> fp16 row-major + fp16 transposed ----------------
__global__ void conv_half_tr_kernel(const float* __restrict__ X,
                                    __half* __restrict__ H, __half* __restrict__ Th)
{
    __shared__ float t[32][33];
    const int b = blockIdx.z;
    const int d0 = blockIdx.x * 32, s0 = blockIdx.y * 32;
    const float* Xp = X + (size_t)b * S_ * D_;
    __half* Hp = H + (size_t)b * S_ * D_;
    for (int i = threadIdx.y; i < 32; i += 8) {
        const size_t sd = (size_t)(s0 + i) * D_ + d0 + threadIdx.x;
        float v = Xp[sd];
        t[i][threadIdx.x] = v;
        Hp[sd] = __float2half_rn(v);
    }
    __syncthreads();
    for (int i = threadIdx.y; i < 32; i += 8) {
        size_t o = (size_t)b * D_ * S_ + (size_t)(d0 + i) * S_ + s0 + threadIdx.x;
        Th[o] = __float2half_rn(t[threadIdx.x][i]);
    }
}

// ---------------- fused: LN-apply + fp32 out + fp16 transposed out ----------------
__global__ void ln_apply_tr_kernel(const float* __restrict__ X, const float* __restrict__ G,
                                   const float* __restrict__ Be,
                                   float* __restrict__ Y, __half* __restrict__ Th)
{
    __shared__ float t[32][33];
    const int b = blockIdx.z;
    const int d0 = blockIdx.x * 32, s0 = blockIdx.y * 32;
    const float mu = g_stats[b * 2], rs = g_stats[b * 2 + 1];
    const float* Xp = X + (size_t)b * S_ * D_;
    float* Yp = Y + (size_t)b * S_ * D_;
    for (int i = threadIdx.y; i < 32; i += 8) {
        const size_t sd = (size_t)(s0 + i) * D_ + d0 + threadIdx.x;
        float y = (Xp[sd] - mu) * rs * G[sd] + Be[sd];
        t[i][threadIdx.x] = y;
        Yp[sd] = y;
    }
    __syncthreads();
    for (int i = threadIdx.y; i < 32; i += 8) {
        size_t o = (size_t)b * D_ * S_ + (size_t)(d0 + i) * S_ + s0 + threadIdx.x;
        Th[o] = __float2half_rn(t[threadIdx.x][i]);
    }
}

// ---------------- LN final reduce ----------------
__global__ void ln_reduce2_kernel()
{
    const int b = blockIdx.x;
    const int t = threadIdx.x;
    double s  = (t < 128) ? g_part[((size_t)b * 256 + t) * 2]     : 0.0;
    double s2 = (t < 128) ? g_part[((size_t)b * 256 + t) * 2 + 1] : 0.0;
    __shared__ double sh[256], sh2[256];
    sh[t] = s; sh2[t] = s2;
    __syncthreads();
    for (int o = 128; o > 0; o >>= 1) {
        if (t < o) { sh[t] += sh[t + o]; sh2[t] += sh2[t + o]; }
        __syncthreads();
    }
    if (t == 0) {
        const double n = (double)S_ * (double)D_;
        double mu  = sh[0] / n;
        double var = sh2[0] / n - mu * mu;
        g_stats[b * 2]     = (float)mu;
        g_stats[b * 2 + 1] = (float)(1.0 / sqrt(var + (double)LN_EPS));
    }
}

// ---------------- vectorized LN-apply (float4/thread) ----------------
__global__ void ln_apply_kernel(const float* __restrict__ X, const float* __restrict__ G,
                                const float* __restrict__ Be, float* __restrict__ Y)
{
    const size_t idx = ((size_t)blockIdx.x * blockDim.x + threadIdx.x) * 4;
    const size_t sd = idx & ((size_t)S_ * D_ - 1);
    const int b = (int)(idx >> 21);
    const float mu = g_stats[b * 2], rs = g_stats[b * 2 + 1];
    float4 xv = *reinterpret_cast<const float4*>(X + idx);
    float4 gv = *reinterpret_cast<const float4*>(G + sd);
    float4 bv = *reinterpret_cast<const float4*>(Be + sd);
    float4 yv;
    yv.x = (xv.x - mu) * rs * gv.x + bv.x;
    yv.y = (xv.y - mu) * rs * gv.y + bv.y;
    yv.z = (xv.z - mu) * rs * gv.z + bv.z;
    yv.w = (xv.w - mu) * rs * gv.w + bv.w;
    *reinterpret_cast<float4*>(Y + idx) = yv;
}

__global__ void ln_apply_half_kernel(const float* __restrict__ X, const float* __restrict__ G,
                                     const float* __restrict__ Be, float* __restrict__ Y,
                                     __half* __restrict__ Yh)
{
    const size_t idx = ((size_t)blockIdx.x * blockDim.x + threadIdx.x) * 4;
    const size_t sd = idx & ((size_t)S_ * D_ - 1);
    const int b = (int)(idx >> 21);
    const float mu = g_stats[b * 2], rs = g_stats[b * 2 + 1];
    float4 xv = *reinterpret_cast<const float4*>(X + idx);
    float4 gv = *reinterpret_cast<const float4*>(G + sd);
    float4 bv = *reinterpret_cast<const float4*>(Be + sd);
    float4 yv;
    yv.x = (xv.x - mu) * rs * gv.x + bv.x;
    yv.y = (xv.y - mu) * rs * gv.y + bv.y;
    yv.z = (xv.z - mu) * rs * gv.z + bv.z;
    yv.w = (xv.w - mu) * rs * gv.w + bv.w;
    *reinterpret_cast<float4*>(Y + idx) = yv;
    __half2 a = __floats2half2_rn(yv.x, yv.y);
    __half2 c = __floats2half2_rn(yv.z, yv.w);
    uint2 hv;
    hv.x = *reinterpret_cast<const uint32_t*>(&a);
    hv.y = *reinterpret_cast<const uint32_t*>(&c);
    *reinterpret_cast<uint2*>(Yh + idx) = hv;
}

// ---------------- orchestration ----------------
extern "C" void kernel_launch(void* const* d_in, const int* in_sizes, int n_in,
                              void* d_out, int out_size)
{
    (void)in_sizes; (void)n_in; (void)out_size;
    const float* x    = (const float*)d_in[0];
    const float* enc  = (const float*)d_in[1];
    const float* Wo1  = (const float*)d_in[2];
    const float* Wo2  = (const float*)d_in[3];
    const float* ln1g = (const float*)d_in[4];
    const float* ln1b = (const float*)d_in[5];
    const float* ln2g = (const float*)d_in[6];
    const float* ln2b = (const float*)d_in[7];
    const float* W1   = (const float*)d_in[8];
    const float* b1   = (const float*)d_in[9];
    const float* W2   = (const float*)d_in[10];
    const float* b2   = (const float*)d_in[11];
    float* out = (float*)d_out;

    float *scores, *t2, *x1, *x2;
    cudaGetSymbolAddress((void**)&scores, g_scores);
    cudaGetSymbolAddress((void**)&t2, g_t2);
    cudaGetSymbolAddress((void**)&x1, g_x1);
    cudaGetSymbolAddress((void**)&x2, g_x2);
    __half *xh, *eh, *vth, *Ph, *t1h, *x2h, *hh;
    __half *wo1h, *wo2h, *w1h, *w2h;
    cudaGetSymbolAddress((void**)&xh, g_xh);
    cudaGetSymbolAddress((void**)&eh, g_eh);
    cudaGetSymbolAddress((void**)&vth, g_vth);
    cudaGetSymbolAddress((void**)&Ph, g_Ph);
    cudaGetSymbolAddress((void**)&t1h, g_t1h);
    cudaGetSymbolAddress((void**)&x2h, g_x2h);
    cudaGetSymbolAddress((void**)&hh, g_hh);
    cudaGetSymbolAddress((void**)&wo1h, g_wo1h); cudaGetSymbolAddress((void**)&wo2h, g_wo2h);
    cudaGetSymbolAddress((void**)&w1h, g_w1h);   cudaGetSymbolAddress((void**)&w2h, g_w2h);

    cudaFuncSetAttribute(gemm_mma<0,1,0,0>, cudaFuncAttributeMaxDynamicSharedMemorySize, SMEM_DYN);
    cudaFuncSetAttribute(gemm_mma<0,3,0,0>, cudaFuncAttributeMaxDynamicSharedMemorySize, SMEM_DYN);
    cudaFuncSetAttribute(gemm_mma<0,2,1,0>, cudaFuncAttributeMaxDynamicSharedMemorySize, SMEM_DYN);
    cudaFuncSetAttribute(gemm_mma<0,0,1,0>, cudaFuncAttributeMaxDynamicSharedMemorySize, SMEM_DYN);
    cudaFuncSetAttribute(gemm_mma<1,0,0,1>, cudaFuncAttributeMaxDynamicSharedMemorySize, SMEM_DYN);
    cudaFuncSetAttribute(gemm_mma<2,0,1,0>, cudaFuncAttributeMaxDynamicSharedMemorySize, SMEM_DYN);
    cudaFuncSetAttribute(gemm_mma<3,0,0,1>, cudaFuncAttributeMaxDynamicSharedMemorySize, SMEM_DYN);

    const dim3 blk(256);
    const dim3 gblk(GT);
    const float scale = 1.0f / sqrtf((float)D_);
    const long long sSS = (long long)S_ * S_;
    const long long sSD = (long long)S_ * D_;
    const long long sDS = (long long)D_ * S_;
    const int lnBlocks4 = (B_ * S_ * D_) / 1024;
    const size_t nBSD = (size_t)B_ * S_ * D_;

    // ---- operand conversions ----
    conv_half_tr_kernel<<<dim3(D_ / 32, S_ / 32, B_), dim3(32, 8)>>>(x, xh, vth);
    half_kernel<<<(int)(nBSD / 1024), blk>>>(enc, eh);
    weights_half_kernel<<<(2 * D_ * D_ + 2 * F_ * D_) / 1024, blk>>>(
        Wo1, Wo2, W1, W2, wo1h, wo2h, w1h, w2h);

    // ---- 1) causal self-attention + Wo1 + residual + ln1 ----
    gemm_mma<0,1,0,0><<<dim3(S_ / BN, S_ / BM, B_), gblk, SMEM_DYN>>>(
        xh, xh, scores, nullptr, nullptr, nullptr,
        S_, S_, D_, scale, sSD, sSD, sSS);
    softmax_half_kernel<1><<<dim3(S_, B_), blk>>>(scores, Ph);
    gemm_mma<0,2,1,0><<<dim3(D_ / BN, S_ / BM, B_), gblk, SMEM_DYN>>>(
        Ph, vth, nullptr, t1h, nullptr, nullptr,
        S_, D_, S_, 1.f, sSS, sDS, sSD);
    gemm_mma<1,0,0,1><<<dim3(D_ / BN, (B_ * S_) / BM, 1), gblk, SMEM_DYN>>>(
        t1h, wo1h, t2, nullptr, x, nullptr,
        B_ * S_, D_, D_, 1.f, 0, 0, 0);
    ln_reduce2_kernel<<<B_, blk>>>();
    ln_apply_tr_kernel<<<dim3(D_ / 32, S_ / 32, B_), dim3(32, 8)>>>(t2, ln1g, ln1b, x1, vth);

    // ---- 2) cross attention (q=k=enc, v=x1): scores symmetric -> half the blocks ----
    gemm_mma<0,3,0,0><<<dim3(S_ / BN, S_ / BM, B_), gblk, SMEM_DYN>>>(
        eh, eh, scores, nullptr, nullptr, nullptr,
        S_, S_, D_, scale, sSD, sSD, sSS);
    softmax_half_kernel<0><<<dim3(S_, B_), blk>>>(scores, Ph);
    gemm_mma<0,0,1,0><<<dim3(D_ / BN, S_ / BM, B_), gblk, SMEM_DYN>>>(
        Ph, vth, nullptr, t1h, nullptr, nullptr,
        S_, D_, S_, 1.f, sSS, sDS, sSD);
    gemm_mma<1,0,0,1><<<dim3(D_ / BN, (B_ * S_) / BM, 1), gblk, SMEM_DYN>>>(
        t1h, wo2h, t2, nullptr, x1, nullptr,
        B_ * S_, D_, D_, 1.f, 0, 0, 0);
    ln_reduce2_kernel<<<B_, blk>>>();
    ln_apply_half_kernel<<<lnBlocks4, blk>>>(t2, ln2g, ln2b, x2, x2h);

    // ---- 3) FFN + residual + ln2 (shared params) ----
    gemm_mma<2,0,1,0><<<dim3(F_ / BN, (B_ * S_) / BM, 1), gblk, SMEM_DYN>>>(
        x2h, w1h, nullptr, hh, nullptr, b1,
        B_ * S_, F_, D_, 1.f, 0, 0, 0);
    gemm_mma<3,0,0,1><<<dim3(D_ / BN, (B_ * S_) / BM, 1), gblk, SMEM_DYN>>>(
        hh, w2h, t2, nullptr, x2, b2,
        B_ * S_, D_, F_, 1.f, 0, 0, 0);
    ln_reduce2_kernel<<<B_, blk>>>();
    ln_apply_kernel<<<lnBlocks4, blk>>>(t2, ln2g, ln2b, out);
}